// round 14
// baseline (speedup 1.0000x reference)
#include <cuda_runtime.h>
#include <math.h>
#include <stdint.h>

#define Bn 256
#define Tn 128
#define Fn 1024
#define Hn 512
#define IN1 1152
#define KSP 32         // k1 K-splits (32-wide slices of the 1024 hs dim)

__device__ float    g_cp[KSP][Bn * Tn];   // k1 partials (D[t,b] slices)
__device__ float    g_e[Bn * Fn];         // logits
__device__ uint32_t g_afrag[8 * 8 * 128]; // A fragments [mt][ks][lane*4] (fp16x2)

__device__ __forceinline__ float tanh_fast(float x) {
    float y; asm("tanh.approx.f32 %0, %1;" : "=f"(y) : "f"(x)); return y;
}
__device__ __forceinline__ uint32_t pack_h2(float hi, float lo) {
    uint32_t d;
    asm("cvt.rn.f16x2.f32 %0, %1, %2;" : "=r"(d) : "f"(hi), "f"(lo));
    return d;
}
__device__ __forceinline__ void mma_f16(float* d, const uint4& a, uint32_t b0, uint32_t b1) {
    asm volatile(
        "mma.sync.aligned.m16n8k16.row.col.f32.f16.f16.f32 "
        "{%0,%1,%2,%3}, {%4,%5,%6,%7}, {%8,%9}, {%0,%1,%2,%3};"
        : "+f"(d[0]), "+f"(d[1]), "+f"(d[2]), "+f"(d[3])
        : "r"(a.x), "r"(a.y), "r"(a.z), "r"(a.w), "r"(b0), "r"(b1));
}

// ---------------------------------------------------------------------------
// k1: c partials via fp16 mma. grid (KSP=32, 8) = 256 CTAs. (R13 measured best)
// CTA: D[t=128, b=32] for one K=32 slice of hs. 2 k-steps, 8 warps (2M x 4N).
// SIDE JOB: blocks (0, y) stage k2's A fragments into g_afrag.
// ---------------------------------------------------------------------------
__global__ __launch_bounds__(256) void k1_mma(
    const float* __restrict__ h, const float* __restrict__ s,
    const float* __restrict__ W1, const float* __restrict__ b1) {
    extern __shared__ uint32_t dynA[];            // A at 0, B at 2048
    int tid = threadIdx.x;
    int w = tid >> 5, lane = tid & 31;
    int wm = w >> 2, wn = w & 3;
    int g = lane >> 2, tq = lane & 3;
    int ksl = blockIdx.x;
    int b0  = blockIdx.y * 32;

    if (ksl == 0) {
        int mt = blockIdx.y;       // 0..7
        const float* r0 = W1 + (size_t)(mt * 16 + g) * IN1;
        const float* r8 = r0 + 8 * IN1;
        int c0 = w * 16 + 2 * tq;  // warp w = k-step
        float2 p00 = *(const float2*)(r0 + c0);
        float2 p10 = *(const float2*)(r8 + c0);
        float2 p01 = *(const float2*)(r0 + c0 + 8);
        float2 p11 = *(const float2*)(r8 + c0 + 8);
        uint4 v;
        v.x = pack_h2(p00.y, p00.x);
        v.y = pack_h2(p10.y, p10.x);
        v.z = pack_h2(p01.y, p01.x);
        v.w = pack_h2(p11.y, p11.x);
        *(uint4*)&g_afrag[(mt * 8 + w) * 128 + lane * 4] = v;
    }

    {
        const float* base = (ksl < 16) ? h : s;
        int joff = (ksl & 15) * 32;
        const float* row = base + (size_t)(b0 + wn * 8 + g) * Hn + joff;
        int ks = wm;               // 0..1
        int k0 = ks * 16 + 2 * tq;
        float2 p0 = *(const float2*)(row + k0);
        float2 p1 = *(const float2*)(row + k0 + 8);
        uint2 bv;
        bv.x = pack_h2(p0.y, p0.x);
        bv.y = pack_h2(p1.y, p1.x);
        *(uint2*)&dynA[2048 + (wn * 2 + ks) * 64 + lane * 2] = bv;
    }
    {
        const float* r0 = W1 + (size_t)(w * 16 + g) * IN1 + Tn + ksl * 32;
        const float* r8 = r0 + 8 * IN1;
        #pragma unroll
        for (int ks = 0; ks < 2; ks++) {
            int c0 = ks * 16 + 2 * tq;
            float2 p00 = *(const float2*)(r0 + c0);
            float2 p10 = *(const float2*)(r8 + c0);
            float2 p01 = *(const float2*)(r0 + c0 + 8);
            float2 p11 = *(const float2*)(r8 + c0 + 8);
            uint4 v;
            v.x = pack_h2(p00.y, p00.x);
            v.y = pack_h2(p10.y, p10.x);
            v.z = pack_h2(p01.y, p01.x);
            v.w = pack_h2(p11.y, p11.x);
            *(uint4*)&dynA[(w * 2 + ks) * 128 + lane * 4] = v;
        }
    }
    __syncthreads();

    float acc[4][4];
    #pragma unroll
    for (int i = 0; i < 4; i++)
        #pragma unroll
        for (int r = 0; r < 4; r++) acc[i][r] = 0.f;

    #pragma unroll
    for (int ks = 0; ks < 2; ks++) {
        uint4 a[4];
        uint2 bf;
        #pragma unroll
        for (int i = 0; i < 4; i++)
            a[i] = *(const uint4*)&dynA[((wm * 4 + i) * 2 + ks) * 128 + lane * 4];
        bf = *(const uint2*)&dynA[2048 + (wn * 2 + ks) * 64 + lane * 2];
        #pragma unroll
        for (int i = 0; i < 4; i++)
            mma_f16(acc[i], a[i], bf.x, bf.y);
    }

    #pragma unroll
    for (int i = 0; i < 4; i++) {
        int t0 = (wm * 4 + i) * 16 + g;
        float bias0 = (ksl == 0) ? __ldg(&b1[t0])     : 0.f;
        float bias1 = (ksl == 0) ? __ldg(&b1[t0 + 8]) : 0.f;
        int bc = b0 + wn * 8 + 2 * tq;
        g_cp[ksl][(bc)     * Tn + t0]     = acc[i][0] + bias0;
        g_cp[ksl][(bc + 1) * Tn + t0]     = acc[i][1] + bias0;
        g_cp[ksl][(bc)     * Tn + t0 + 8] = acc[i][2] + bias1;
        g_cp[ksl][(bc + 1) * Tn + t0 + 8] = acc[i][3] + bias1;
    }
}

// ---------------------------------------------------------------------------
// k2: fp16 mma, 512 threads = 16 warps (4M x 4N), warp tile 32t x 32f.
// R12 structure; B fragments stored ks-PAIRED so compute uses LDS.128
// (one load = 2 k-steps). A from g_afrag (L1-hot LDG.128).
// Dynamic smem (u32): B frags [16 nt][4 kp][128] = 8192 (32KB).
// ---------------------------------------------------------------------------
__global__ __launch_bounds__(512, 2) void k2_main(
    const float* __restrict__ x, const float* __restrict__ W1,
    const float* __restrict__ W2, const float* __restrict__ b2) {
    extern __shared__ uint32_t dyn[];   // B frags at 0
    __shared__ float c_s[Tn], w2_s[Tn];
    __shared__ float red2[4][128];

    int tid = threadIdx.x;
    int w = tid >> 5, lane = tid & 31;
    int wm = w >> 2, wn = w & 3;
    int g = lane >> 2, tq = lane & 3;
    int b  = blockIdx.y;
    int f0 = blockIdx.x * 128;

    // ---- c/w2 loads first: latency hides under the staging burst ----
    if (tid < Tn) {
        float c = 0.f;
        #pragma unroll
        for (int k = 0; k < KSP; k++) c += g_cp[k][b * Tn + tid];
        c_s[tid]  = c;
        w2_s[tid] = __ldg(&W2[tid]);
    }

    // ---- stage B: warp w -> nt = w; ks-paired fragment layout ----
    {
        const float* col = x + (size_t)b * Tn * Fn + f0 + w * 8 + g;
        #pragma unroll
        for (int ks = 0; ks < 8; ks++) {
            int k0 = ks * 16 + 2 * tq;
            float v00 = __ldg(col + (size_t)k0 * Fn);
            float v01 = __ldg(col + (size_t)(k0 + 1) * Fn);
            float v10 = __ldg(col + (size_t)(k0 + 8) * Fn);
            float v11 = __ldg(col + (size_t)(k0 + 9) * Fn);
            uint2 bv;
            bv.x = pack_h2(v01, v00);
            bv.y = pack_h2(v11, v10);
            *(uint2*)&dyn[(w * 4 + (ks >> 1)) * 128 + lane * 4 + (ks & 1) * 2] = bv;
        }
    }
    __syncthreads();

    // ---- compute: 4 kp x 2 half x (2 mt x 4 nt) mma ----
    float acc[2][4][4];
    #pragma unroll
    for (int i = 0; i < 2; i++)
        #pragma unroll
        for (int j = 0; j < 4; j++)
            #pragma unroll
            for (int r = 0; r < 4; r++) acc[i][j][r] = 0.f;

    #pragma unroll
    for (int kp = 0; kp < 4; kp++) {
        uint4 bq[4];
        #pragma unroll
        for (int j = 0; j < 4; j++)
            bq[j] = *(const uint4*)&dyn[((wn * 4 + j) * 4 + kp) * 128 + lane * 4];
        #pragma unroll
        for (int hh = 0; hh < 2; hh++) {
            int ks = kp * 2 + hh;
            uint4 a[2];
            #pragma unroll
            for (int i = 0; i < 2; i++)
                a[i] = __ldg((const uint4*)&g_afrag[((wm * 2 + i) * 8 + ks) * 128 + lane * 4]);
            #pragma unroll
            for (int i = 0; i < 2; i++)
                #pragma unroll
                for (int j = 0; j < 4; j++) {
                    if (hh == 0) mma_f16(acc[i][j], a[i], bq[j].x, bq[j].y);
                    else         mma_f16(acc[i][j], a[i], bq[j].z, bq[j].w);
                }
        }
    }

    // ---- epilogue: e[f] = b2 + sum_t W2[t] * tanh(D[t][f] + c[t]) ----
    float b2v = __ldg(&b2[0]);
    float es[4][2];
    #pragma unroll
    for (int j = 0; j < 4; j++) { es[j][0] = 0.f; es[j][1] = 0.f; }
    #pragma unroll
    for (int i = 0; i < 2; i++) {
        int t0 = (wm * 2 + i) * 16 + g;
        float c0 = c_s[t0],     w0 = w2_s[t0];
        float c1 = c_s[t0 + 8], w1 = w2_s[t0 + 8];
        #pragma unroll
        for (int j = 0; j < 4; j++) {
            es[j][0] += w0 * tanh_fast(acc[i][j][0] + c0)
                      + w1 * tanh_fast(acc[i][j][2] + c1);
            es[j][1] += w0 * tanh_fast(acc[i][j][1] + c0)
                      + w1 * tanh_fast(acc[i][j][3] + c1);
        }
    }
    #pragma unroll
    for (int j = 0; j < 4; j++)
        #pragma unroll
        for (int s2 = 0; s2 < 2; s2++) {
            float v = es[j][s2];
            v += __shfl_xor_sync(0xffffffffu, v, 4);
            v += __shfl_xor_sync(0xffffffffu, v, 8);
            v += __shfl_xor_sync(0xffffffffu, v, 16);
            es[j][s2] = v;
        }
    if (lane < 4) {
        #pragma unroll
        for (int j = 0; j < 4; j++) {
            int fl = (wn * 4 + j) * 8 + 2 * lane;
            red2[wm][fl]     = es[j][0];
            red2[wm][fl + 1] = es[j][1];
        }
    }
    __syncthreads();
    if (tid < 128)
        g_e[b * Fn + f0 + tid] = red2[0][tid] + red2[1][tid]
                               + red2[2][tid] + red2[3][tid] + b2v;
}

// ---------------------------------------------------------------------------
// k3: softmax over f per batch
// ---------------------------------------------------------------------------
__global__ void k3_softmax(float* __restrict__ out) {
    __shared__ float smr[256];
    int b = blockIdx.x, tid = threadIdx.x;
    const float* eb = g_e + b * Fn;
    float v[4];
    float m = -1e30f;
    #pragma unroll
    for (int i = 0; i < 4; i++) { v[i] = eb[tid + i * 256]; m = fmaxf(m, v[i]); }
    smr[tid] = m; __syncthreads();
    for (int st = 128; st > 0; st >>= 1) {
        if (tid < st) smr[tid] = fmaxf(smr[tid], smr[tid + st]);
        __syncthreads();
    }
    m = smr[0];
    __syncthreads();
    float sum = 0.f;
    #pragma unroll
    for (int i = 0; i < 4; i++) { v[i] = __expf(v[i] - m); sum += v[i]; }
    smr[tid] = sum; __syncthreads();
    for (int st = 128; st > 0; st >>= 1) {
        if (tid < st) smr[tid] += smr[tid + st];
        __syncthreads();
    }
    float inv = 1.f / smr[0];
    #pragma unroll
    for (int i = 0; i < 4; i++) out[b * Fn + tid + i * 256] = v[i] * inv;
}

extern "C" void kernel_launch(void* const* d_in, const int* in_sizes, int n_in,
                              void* d_out, int out_size) {
    const float* h  = (const float*)d_in[0];
    const float* s  = (const float*)d_in[1];
    const float* x  = (const float*)d_in[2];
    const float* W1 = (const float*)d_in[3];
    const float* b1 = (const float*)d_in[4];
    const float* W2 = (const float*)d_in[5];
    const float* b2 = (const float*)d_in[6];
    float* out = (float*)d_out;

    static int init_done = 0;
    if (!init_done) {
        cudaFuncSetAttribute(k2_main, cudaFuncAttributeMaxDynamicSharedMemorySize,
                             32768);
        cudaFuncSetAttribute(k1_mma, cudaFuncAttributeMaxDynamicSharedMemorySize,
                             2560 * (int)sizeof(uint32_t));
        init_done = 1;
    }

    dim3 g1(KSP, 8);
    k1_mma<<<g1, 256, 2560 * sizeof(uint32_t)>>>(h, s, W1, b1);
    dim3 g2(Fn / 128, Bn);
    k2_main<<<g2, 512, 32768>>>(x, W1, W2, b2);
    k3_softmax<<<Bn, 256>>>(out);
}

// round 15
// speedup vs baseline: 1.1062x; 1.1062x over previous
#include <cuda_runtime.h>
#include <math.h>
#include <stdint.h>

#define Bn 256
#define Tn 128
#define Fn 1024
#define Hn 512
#define IN1 1152
#define KSP 32         // k1 K-splits (32-wide slices of the 1024 hs dim)

__device__ float    g_cp[KSP][Bn * Tn];   // k1 partials (D[t,b] slices)
__device__ float    g_e[Bn * Fn];         // logits
__device__ uint32_t g_afrag[8 * 8 * 128]; // A fragments [mt][ks][lane*4] (fp16x2)

__device__ __forceinline__ float tanh_fast(float x) {
    float y; asm("tanh.approx.f32 %0, %1;" : "=f"(y) : "f"(x)); return y;
}
__device__ __forceinline__ uint32_t pack_h2(float hi, float lo) {
    uint32_t d;
    asm("cvt.rn.f16x2.f32 %0, %1, %2;" : "=r"(d) : "f"(hi), "f"(lo));
    return d;
}
__device__ __forceinline__ void mma_f16(float* d, const uint4& a, uint32_t b0, uint32_t b1) {
    asm volatile(
        "mma.sync.aligned.m16n8k16.row.col.f32.f16.f16.f32 "
        "{%0,%1,%2,%3}, {%4,%5,%6,%7}, {%8,%9}, {%0,%1,%2,%3};"
        : "+f"(d[0]), "+f"(d[1]), "+f"(d[2]), "+f"(d[3])
        : "r"(a.x), "r"(a.y), "r"(a.z), "r"(a.w), "r"(b0), "r"(b1));
}

// ---------------------------------------------------------------------------
// k1: c partials via fp16 mma, BARRIER-FREE. grid (KSP=32, 8) = 256 CTAs.
// Every fragment element is per-lane -> direct LDG into fragment registers.
// No smem, no __syncthreads: chain = LDG -> pack -> mma -> STG.
// A (W1 slice) is re-read per M-warp but L2-hot. 8 warps = 2(M) x 4(N).
// SIDE JOB: blocks (0, y) stage k2's A fragments into g_afrag.
// ---------------------------------------------------------------------------
__global__ __launch_bounds__(256) void k1_mma(
    const float* __restrict__ h, const float* __restrict__ s,
    const float* __restrict__ W1, const float* __restrict__ b1) {
    int tid = threadIdx.x;
    int w = tid >> 5, lane = tid & 31;
    int wm = w >> 2, wn = w & 3;
    int g = lane >> 2, tq = lane & 3;
    int ksl = blockIdx.x;          // K slice (0..31): j = ksl*32 + kk
    int b0  = blockIdx.y * 32;

    // ---- side job: stage k2's A fragments (8 CTAs of slice 0, 1 mt each) ----
    if (ksl == 0) {
        int mt = blockIdx.y;       // 0..7
        const float* r0 = W1 + (size_t)(mt * 16 + g) * IN1;
        const float* r8 = r0 + 8 * IN1;
        int c0 = w * 16 + 2 * tq;  // warp w = k-step
        float2 p00 = *(const float2*)(r0 + c0);
        float2 p10 = *(const float2*)(r8 + c0);
        float2 p01 = *(const float2*)(r0 + c0 + 8);
        float2 p11 = *(const float2*)(r8 + c0 + 8);
        uint4 v;
        v.x = pack_h2(p00.y, p00.x);
        v.y = pack_h2(p10.y, p10.x);
        v.z = pack_h2(p01.y, p01.x);
        v.w = pack_h2(p11.y, p11.x);
        *(uint4*)&g_afrag[(mt * 8 + w) * 128 + lane * 4] = v;
    }

    // ---- B fragments direct (h/s rows, k-contiguous) ----
    uint2 bf[2];
    {
        const float* base = (ksl < 16) ? h : s;
        int joff = (ksl & 15) * 32;
        const float* row = base + (size_t)(b0 + wn * 8 + g) * Hn + joff;
        #pragma unroll
        for (int ks = 0; ks < 2; ks++) {
            int k0 = ks * 16 + 2 * tq;
            float2 p0 = *(const float2*)(row + k0);
            float2 p1 = *(const float2*)(row + k0 + 8);
            bf[ks].x = pack_h2(p0.y, p0.x);
            bf[ks].y = pack_h2(p1.y, p1.x);
        }
    }

    // ---- A fragments direct + mma ----
    float acc[4][4];
    #pragma unroll
    for (int i = 0; i < 4; i++)
        #pragma unroll
        for (int r = 0; r < 4; r++) acc[i][r] = 0.f;

    #pragma unroll
    for (int i = 0; i < 4; i++) {
        int t0 = (wm * 4 + i) * 16 + g;
        const float* r0 = W1 + (size_t)t0 * IN1 + Tn + ksl * 32;
        const float* r8 = r0 + 8 * IN1;
        #pragma unroll
        for (int ks = 0; ks < 2; ks++) {
            int c0 = ks * 16 + 2 * tq;
            float2 p00 = *(const float2*)(r0 + c0);
            float2 p10 = *(const float2*)(r8 + c0);
            float2 p01 = *(const float2*)(r0 + c0 + 8);
            float2 p11 = *(const float2*)(r8 + c0 + 8);
            uint4 a;
            a.x = pack_h2(p00.y, p00.x);
            a.y = pack_h2(p10.y, p10.x);
            a.z = pack_h2(p01.y, p01.x);
            a.w = pack_h2(p11.y, p11.x);
            mma_f16(acc[i], a, bf[ks].x, bf[ks].y);
        }
    }

    // ---- store partials: D[t, b] -> g_cp[ksl][b*Tn + t]  (+ b1 on slice 0) ----
    #pragma unroll
    for (int i = 0; i < 4; i++) {
        int t0 = (wm * 4 + i) * 16 + g;
        float bias0 = (ksl == 0) ? __ldg(&b1[t0])     : 0.f;
        float bias1 = (ksl == 0) ? __ldg(&b1[t0 + 8]) : 0.f;
        int bc = b0 + wn * 8 + 2 * tq;
        g_cp[ksl][(bc)     * Tn + t0]     = acc[i][0] + bias0;
        g_cp[ksl][(bc + 1) * Tn + t0]     = acc[i][1] + bias0;
        g_cp[ksl][(bc)     * Tn + t0 + 8] = acc[i][2] + bias1;
        g_cp[ksl][(bc + 1) * Tn + t0 + 8] = acc[i][3] + bias1;
    }
}

// ---------------------------------------------------------------------------
// k2: fp16 mma, 512 threads = 16 warps (4M x 4N), warp tile 32t x 32f.
// EXACT R12 champion structure. B staged to smem frags (warp w -> nt = w);
// A from g_afrag (L1-hot LDG.128).
// Dynamic smem (u32): B frags [16 nt][8 ks][64] = 8192 (32KB).
// ---------------------------------------------------------------------------
__global__ __launch_bounds__(512, 2) void k2_main(
    const float* __restrict__ x, const float* __restrict__ W1,
    const float* __restrict__ W2, const float* __restrict__ b2) {
    extern __shared__ uint32_t dyn[];   // B frags at 0
    __shared__ float c_s[Tn], w2_s[Tn];
    __shared__ float red2[4][128];

    int tid = threadIdx.x;
    int w = tid >> 5, lane = tid & 31;
    int wm = w >> 2, wn = w & 3;
    int g = lane >> 2, tq = lane & 3;
    int b  = blockIdx.y;
    int f0 = blockIdx.x * 128;

    // ---- stage B: warp w handles nt = w (f cols w*8 .. w*8+7) ----
    {
        const float* col = x + (size_t)b * Tn * Fn + f0 + w * 8 + g;
        #pragma unroll
        for (int ks = 0; ks < 8; ks++) {
            int k0 = ks * 16 + 2 * tq;
            float v00 = __ldg(col + (size_t)k0 * Fn);
            float v01 = __ldg(col + (size_t)(k0 + 1) * Fn);
            float v10 = __ldg(col + (size_t)(k0 + 8) * Fn);
            float v11 = __ldg(col + (size_t)(k0 + 9) * Fn);
            uint2 bv;
            bv.x = pack_h2(v01, v00);
            bv.y = pack_h2(v11, v10);
            *(uint2*)&dyn[(w * 8 + ks) * 64 + lane * 2] = bv;
        }
    }

    if (tid < Tn) {
        float c = 0.f;
        #pragma unroll
        for (int k = 0; k < KSP; k++) c += g_cp[k][b * Tn + tid];
        c_s[tid]  = c;
        w2_s[tid] = __ldg(&W2[tid]);
    }
    __syncthreads();

    // ---- compute: 8 k-steps x (2 mt x 4 nt) mma ----
    float acc[2][4][4];
    #pragma unroll
    for (int i = 0; i < 2; i++)
        #pragma unroll
        for (int j = 0; j < 4; j++)
            #pragma unroll
            for (int r = 0; r < 4; r++) acc[i][j][r] = 0.f;

    #pragma unroll
    for (int ks = 0; ks < 8; ks++) {
        uint4 a[2];
        uint2 bfr[4];
        #pragma unroll
        for (int i = 0; i < 2; i++)
            a[i] = __ldg((const uint4*)&g_afrag[((wm * 2 + i) * 8 + ks) * 128 + lane * 4]);
        #pragma unroll
        for (int j = 0; j < 4; j++)
            bfr[j] = *(const uint2*)&dyn[((wn * 4 + j) * 8 + ks) * 64 + lane * 2];
        #pragma unroll
        for (int i = 0; i < 2; i++)
            #pragma unroll
            for (int j = 0; j < 4; j++)
                mma_f16(acc[i][j], a[i], bfr[j].x, bfr[j].y);
    }

    // ---- epilogue: e[f] = b2 + sum_t W2[t] * tanh(D[t][f] + c[t]) ----
    float b2v = __ldg(&b2[0]);
    float es[4][2];
    #pragma unroll
    for (int j = 0; j < 4; j++) { es[j][0] = 0.f; es[j][1] = 0.f; }
    #pragma unroll
    for (int i = 0; i < 2; i++) {
        int t0 = (wm * 2 + i) * 16 + g;
        float c0 = c_s[t0],     w0 = w2_s[t0];
        float c1 = c_s[t0 + 8], w1 = w2_s[t0 + 8];
        #pragma unroll
        for (int j = 0; j < 4; j++) {
            es[j][0] += w0 * tanh_fast(acc[i][j][0] + c0)
                      + w1 * tanh_fast(acc[i][j][2] + c1);
            es[j][1] += w0 * tanh_fast(acc[i][j][1] + c0)
                      + w1 * tanh_fast(acc[i][j][3] + c1);
        }
    }
    #pragma unroll
    for (int j = 0; j < 4; j++)
        #pragma unroll
        for (int s2 = 0; s2 < 2; s2++) {
            float v = es[j][s2];
            v += __shfl_xor_sync(0xffffffffu, v, 4);
            v += __shfl_xor_sync(0xffffffffu, v, 8);
            v += __shfl_xor_sync(0xffffffffu, v, 16);
            es[j][s2] = v;
        }
    if (lane < 4) {
        #pragma unroll
        for (int j = 0; j < 4; j++) {
            int fl = (wn * 4 + j) * 8 + 2 * lane;
            red2[wm][fl]     = es[j][0];
            red2[wm][fl + 1] = es[j][1];
        }
    }
    __syncthreads();
    if (tid < 128)
        g_e[b * Fn + f0 + tid] = red2[0][tid] + red2[1][tid]
                               + red2[2][tid] + red2[3][tid] + b2v;
}

// ---------------------------------------------------------------------------
// k3: softmax over f per batch
// ---------------------------------------------------------------------------
__global__ void k3_softmax(float* __restrict__ out) {
    __shared__ float smr[256];
    int b = blockIdx.x, tid = threadIdx.x;
    const float* eb = g_e + b * Fn;
    float v[4];
    float m = -1e30f;
    #pragma unroll
    for (int i = 0; i < 4; i++) { v[i] = eb[tid + i * 256]; m = fmaxf(m, v[i]); }
    smr[tid] = m; __syncthreads();
    for (int st = 128; st > 0; st >>= 1) {
        if (tid < st) smr[tid] = fmaxf(smr[tid], smr[tid + st]);
        __syncthreads();
    }
    m = smr[0];
    __syncthreads();
    float sum = 0.f;
    #pragma unroll
    for (int i = 0; i < 4; i++) { v[i] = __expf(v[i] - m); sum += v[i]; }
    smr[tid] = sum; __syncthreads();
    for (int st = 128; st > 0; st >>= 1) {
        if (tid < st) smr[tid] += smr[tid + st];
        __syncthreads();
    }
    float inv = 1.f / smr[0];
    #pragma unroll
    for (int i = 0; i < 4; i++) out[b * Fn + tid + i * 256] = v[i] * inv;
}

extern "C" void kernel_launch(void* const* d_in, const int* in_sizes, int n_in,
                              void* d_out, int out_size) {
    const float* h  = (const float*)d_in[0];
    const float* s  = (const float*)d_in[1];
    const float* x  = (const float*)d_in[2];
    const float* W1 = (const float*)d_in[3];
    const float* b1 = (const float*)d_in[4];
    const float* W2 = (const float*)d_in[5];
    const float* b2 = (const float*)d_in[6];
    float* out = (float*)d_out;

    static int init_done = 0;
    if (!init_done) {
        cudaFuncSetAttribute(k2_main, cudaFuncAttributeMaxDynamicSharedMemorySize,
                             32768);
        init_done = 1;
    }

    dim3 g1(KSP, 8);
    k1_mma<<<g1, 256>>>(h, s, W1, b1);
    dim3 g2(Fn / 128, Bn);
    k2_main<<<g2, 512, 32768>>>(x, W1, W2, b2);
    k3_softmax<<<Bn, 256>>>(out);
}

// round 16
// speedup vs baseline: 1.1773x; 1.0643x over previous
#include <cuda_runtime.h>
#include <math.h>
#include <stdint.h>

#define Bn 256
#define Tn 128
#define Fn 1024
#define Hn 512
#define IN1 1152
#define KSP 32         // k1 K-splits (32-wide slices of the 1024 hs dim)

__device__ float    g_cp[KSP][Bn * Tn];   // k1 partials (D[t,b] slices)
__device__ float    g_e[Bn * Fn];         // logits
__device__ uint32_t g_afrag[8 * 8 * 128]; // A fragments [mt][ks][lane*4] (fp16x2)

__device__ __forceinline__ float tanh_fast(float x) {
    float y; asm("tanh.approx.f32 %0, %1;" : "=f"(y) : "f"(x)); return y;
}
__device__ __forceinline__ uint32_t pack_h2(float hi, float lo) {
    uint32_t d;
    asm("cvt.rn.f16x2.f32 %0, %1, %2;" : "=r"(d) : "f"(hi), "f"(lo));
    return d;
}
__device__ __forceinline__ void mma_f16(float* d, const uint4& a, uint32_t b0, uint32_t b1) {
    asm volatile(
        "mma.sync.aligned.m16n8k16.row.col.f32.f16.f16.f32 "
        "{%0,%1,%2,%3}, {%4,%5,%6,%7}, {%8,%9}, {%0,%1,%2,%3};"
        : "+f"(d[0]), "+f"(d[1]), "+f"(d[2]), "+f"(d[3])
        : "r"(a.x), "r"(a.y), "r"(a.z), "r"(a.w), "r"(b0), "r"(b1));
}

// ---------------------------------------------------------------------------
// k1: c partials via fp16 mma. grid (KSP=32, 8) = 256 CTAs.
// EXACT R13/R14 structure (best measured: 6.40us).
// SIDE JOB: blocks (0, y) stage k2's A fragments into g_afrag.
// ---------------------------------------------------------------------------
__global__ __launch_bounds__(256) void k1_mma(
    const float* __restrict__ h, const float* __restrict__ s,
    const float* __restrict__ W1, const float* __restrict__ b1) {
    extern __shared__ uint32_t dynA[];            // A at 0, B at 2048
    int tid = threadIdx.x;
    int w = tid >> 5, lane = tid & 31;
    int wm = w >> 2, wn = w & 3;
    int g = lane >> 2, tq = lane & 3;
    int ksl = blockIdx.x;
    int b0  = blockIdx.y * 32;

    if (ksl == 0) {
        int mt = blockIdx.y;       // 0..7
        const float* r0 = W1 + (size_t)(mt * 16 + g) * IN1;
        const float* r8 = r0 + 8 * IN1;
        int c0 = w * 16 + 2 * tq;  // warp w = k-step
        float2 p00 = *(const float2*)(r0 + c0);
        float2 p10 = *(const float2*)(r8 + c0);
        float2 p01 = *(const float2*)(r0 + c0 + 8);
        float2 p11 = *(const float2*)(r8 + c0 + 8);
        uint4 v;
        v.x = pack_h2(p00.y, p00.x);
        v.y = pack_h2(p10.y, p10.x);
        v.z = pack_h2(p01.y, p01.x);
        v.w = pack_h2(p11.y, p11.x);
        *(uint4*)&g_afrag[(mt * 8 + w) * 128 + lane * 4] = v;
    }

    {
        const float* base = (ksl < 16) ? h : s;
        int joff = (ksl & 15) * 32;
        const float* row = base + (size_t)(b0 + wn * 8 + g) * Hn + joff;
        int ks = wm;               // 0..1
        int k0 = ks * 16 + 2 * tq;
        float2 p0 = *(const float2*)(row + k0);
        float2 p1 = *(const float2*)(row + k0 + 8);
        uint2 bv;
        bv.x = pack_h2(p0.y, p0.x);
        bv.y = pack_h2(p1.y, p1.x);
        *(uint2*)&dynA[2048 + (wn * 2 + ks) * 64 + lane * 2] = bv;
    }
    {
        const float* r0 = W1 + (size_t)(w * 16 + g) * IN1 + Tn + ksl * 32;
        const float* r8 = r0 + 8 * IN1;
        #pragma unroll
        for (int ks = 0; ks < 2; ks++) {
            int c0 = ks * 16 + 2 * tq;
            float2 p00 = *(const float2*)(r0 + c0);
            float2 p10 = *(const float2*)(r8 + c0);
            float2 p01 = *(const float2*)(r0 + c0 + 8);
            float2 p11 = *(const float2*)(r8 + c0 + 8);
            uint4 v;
            v.x = pack_h2(p00.y, p00.x);
            v.y = pack_h2(p10.y, p10.x);
            v.z = pack_h2(p01.y, p01.x);
            v.w = pack_h2(p11.y, p11.x);
            *(uint4*)&dynA[(w * 2 + ks) * 128 + lane * 4] = v;
        }
    }
    __syncthreads();

    float acc[4][4];
    #pragma unroll
    for (int i = 0; i < 4; i++)
        #pragma unroll
        for (int r = 0; r < 4; r++) acc[i][r] = 0.f;

    #pragma unroll
    for (int ks = 0; ks < 2; ks++) {
        uint4 a[4];
        uint2 bf;
        #pragma unroll
        for (int i = 0; i < 4; i++)
            a[i] = *(const uint4*)&dynA[((wm * 4 + i) * 2 + ks) * 128 + lane * 4];
        bf = *(const uint2*)&dynA[2048 + (wn * 2 + ks) * 64 + lane * 2];
        #pragma unroll
        for (int i = 0; i < 4; i++)
            mma_f16(acc[i], a[i], bf.x, bf.y);
    }

    #pragma unroll
    for (int i = 0; i < 4; i++) {
        int t0 = (wm * 4 + i) * 16 + g;
        float bias0 = (ksl == 0) ? __ldg(&b1[t0])     : 0.f;
        float bias1 = (ksl == 0) ? __ldg(&b1[t0 + 8]) : 0.f;
        int bc = b0 + wn * 8 + 2 * tq;
        g_cp[ksl][(bc)     * Tn + t0]     = acc[i][0] + bias0;
        g_cp[ksl][(bc + 1) * Tn + t0]     = acc[i][1] + bias0;
        g_cp[ksl][(bc)     * Tn + t0 + 8] = acc[i][2] + bias1;
        g_cp[ksl][(bc + 1) * Tn + t0 + 8] = acc[i][3] + bias1;
    }
}

// ---------------------------------------------------------------------------
// k2: fp16 mma, 256 threads = 8 warps (4M x 2N), warp tile 32t x 32f,
// f-tile 64 -> grid (16, 256) = 4096 CTAs, 4 CTAs/SM for phase stagger.
// Same per-thread staging/compute pattern as the R12 champion.
// Dynamic smem (u32): B frags [8 nt][8 ks][64] = 4096 (16KB).
// ---------------------------------------------------------------------------
__global__ __launch_bounds__(256, 4) void k2_main(
    const float* __restrict__ x, const float* __restrict__ W1,
    const float* __restrict__ W2, const float* __restrict__ b2) {
    extern __shared__ uint32_t dyn[];   // B frags at 0
    __shared__ float c_s[Tn], w2_s[Tn];
    __shared__ float red2[4][64];

    int tid = threadIdx.x;
    int w = tid >> 5, lane = tid & 31;
    int wm = w >> 1, wn = w & 1;        // 4 M-groups x 2 N-groups
    int g = lane >> 2, tq = lane & 3;
    int b  = blockIdx.y;
    int f0 = blockIdx.x * 64;

    // ---- stage B: warp w handles nt = w (f cols w*8 .. w*8+7) ----
    {
        const float* col = x + (size_t)b * Tn * Fn + f0 + w * 8 + g;
        #pragma unroll
        for (int ks = 0; ks < 8; ks++) {
            int k0 = ks * 16 + 2 * tq;
            float v00 = __ldg(col + (size_t)k0 * Fn);
            float v01 = __ldg(col + (size_t)(k0 + 1) * Fn);
            float v10 = __ldg(col + (size_t)(k0 + 8) * Fn);
            float v11 = __ldg(col + (size_t)(k0 + 9) * Fn);
            uint2 bv;
            bv.x = pack_h2(v01, v00);
            bv.y = pack_h2(v11, v10);
            *(uint2*)&dyn[(w * 8 + ks) * 64 + lane * 2] = bv;
        }
    }

    if (tid < Tn) {
        float c = 0.f;
        #pragma unroll
        for (int k = 0; k < KSP; k++) c += g_cp[k][b * Tn + tid];
        c_s[tid]  = c;
        w2_s[tid] = __ldg(&W2[tid]);
    }
    __syncthreads();

    // ---- compute: 8 k-steps x (2 mt x 4 nt) mma ----
    float acc[2][4][4];
    #pragma unroll
    for (int i = 0; i < 2; i++)
        #pragma unroll
        for (int j = 0; j < 4; j++)
            #pragma unroll
            for (int r = 0; r < 4; r++) acc[i][j][r] = 0.f;

    #pragma unroll
    for (int ks = 0; ks < 8; ks++) {
        uint4 a[2];
        uint2 bfr[4];
        #pragma unroll
        for (int i = 0; i < 2; i++)
            a[i] = __ldg((const uint4*)&g_afrag[((wm * 2 + i) * 8 + ks) * 128 + lane * 4]);
        #pragma unroll
        for (int j = 0; j < 4; j++)
            bfr[j] = *(const uint2*)&dyn[((wn * 4 + j) * 8 + ks) * 64 + lane * 2];
        #pragma unroll
        for (int i = 0; i < 2; i++)
            #pragma unroll
            for (int j = 0; j < 4; j++)
                mma_f16(acc[i][j], a[i], bfr[j].x, bfr[j].y);
    }

    // ---- epilogue: e[f] = b2 + sum_t W2[t] * tanh(D[t][f] + c[t]) ----
    float b2v = __ldg(&b2[0]);
    float es[4][2];
    #pragma unroll
    for (int j = 0; j < 4; j++) { es[j][0] = 0.f; es[j][1] = 0.f; }
    #pragma unroll
    for (int i = 0; i < 2; i++) {
        int t0 = (wm * 2 + i) * 16 + g;
        float c0 = c_s[t0],     w0 = w2_s[t0];
        float c1 = c_s[t0 + 8], w1 = w2_s[t0 + 8];
        #pragma unroll
        for (int j = 0; j < 4; j++) {
            es[j][0] += w0 * tanh_fast(acc[i][j][0] + c0)
                      + w1 * tanh_fast(acc[i][j][2] + c1);
            es[j][1] += w0 * tanh_fast(acc[i][j][1] + c0)
                      + w1 * tanh_fast(acc[i][j][3] + c1);
        }
    }
    #pragma unroll
    for (int j = 0; j < 4; j++)
        #pragma unroll
        for (int s2 = 0; s2 < 2; s2++) {
            float v = es[j][s2];
            v += __shfl_xor_sync(0xffffffffu, v, 4);
            v += __shfl_xor_sync(0xffffffffu, v, 8);
            v += __shfl_xor_sync(0xffffffffu, v, 16);
            es[j][s2] = v;
        }
    if (lane < 4) {
        #pragma unroll
        for (int j = 0; j < 4; j++) {
            int fl = (wn * 4 + j) * 8 + 2 * lane;
            red2[wm][fl]     = es[j][0];
            red2[wm][fl + 1] = es[j][1];
        }
    }
    __syncthreads();
    if (tid < 64)
        g_e[b * Fn + f0 + tid] = red2[0][tid] + red2[1][tid]
                               + red2[2][tid] + red2[3][tid] + b2v;
}

// ---------------------------------------------------------------------------
// k3: softmax over f per batch
// ---------------------------------------------------------------------------
__global__ void k3_softmax(float* __restrict__ out) {
    __shared__ float smr[256];
    int b = blockIdx.x, tid = threadIdx.x;
    const float* eb = g_e + b * Fn;
    float v[4];
    float m = -1e30f;
    #pragma unroll
    for (int i = 0; i < 4; i++) { v[i] = eb[tid + i * 256]; m = fmaxf(m, v[i]); }
    smr[tid] = m; __syncthreads();
    for (int st = 128; st > 0; st >>= 1) {
        if (tid < st) smr[tid] = fmaxf(smr[tid], smr[tid + st]);
        __syncthreads();
    }
    m = smr[0];
    __syncthreads();
    float sum = 0.f;
    #pragma unroll
    for (int i = 0; i < 4; i++) { v[i] = __expf(v[i] - m); sum += v[i]; }
    smr[tid] = sum; __syncthreads();
    for (int st = 128; st > 0; st >>= 1) {
        if (tid < st) smr[tid] += smr[tid + st];
        __syncthreads();
    }
    float inv = 1.f / smr[0];
    #pragma unroll
    for (int i = 0; i < 4; i++) out[b * Fn + tid + i * 256] = v[i] * inv;
}

extern "C" void kernel_launch(void* const* d_in, const int* in_sizes, int n_in,
                              void* d_out, int out_size) {
    const float* h  = (const float*)d_in[0];
    const float* s  = (const float*)d_in[1];
    const float* x  = (const float*)d_in[2];
    const float* W1 = (const float*)d_in[3];
    const float* b1 = (const float*)d_in[4];
    const float* W2 = (const float*)d_in[5];
    const float* b2 = (const float*)d_in[6];
    float* out = (float*)d_out;

    static int init_done = 0;
    if (!init_done) {
        cudaFuncSetAttribute(k2_main, cudaFuncAttributeMaxDynamicSharedMemorySize,
                             16384);
        cudaFuncSetAttribute(k1_mma, cudaFuncAttributeMaxDynamicSharedMemorySize,
                             2560 * (int)sizeof(uint32_t));
        init_done = 1;
    }

    dim3 g1(KSP, 8);
    k1_mma<<<g1, 256, 2560 * sizeof(uint32_t)>>>(h, s, W1, b1);
    dim3 g2(Fn / 64, Bn);
    k2_main<<<g2, 256, 16384>>>(x, W1, W2, b2);
    k3_softmax<<<Bn, 256>>>(out);
}